// round 2
// baseline (speedup 1.0000x reference)
#include <cuda_runtime.h>

typedef unsigned long long ull;

// Scratch: processed states, duplicated per element ({p,p} pairs) so the GEMM
// can load packed f32x2 broadcast multiplicands straight from smem.
// 4096 rows x 32 floats = 512 KB.
__device__ float g_P[4096 * 32];

__device__ __forceinline__ ull pack2(float lo, float hi) {
    ull r; asm("mov.b64 %0, {%1, %2};" : "=l"(r) : "f"(lo), "f"(hi)); return r;
}
__device__ __forceinline__ void unpack2(ull v, float& lo, float& hi) {
    asm("mov.b64 {%0, %1}, %2;" : "=f"(lo), "=f"(hi) : "l"(v));
}
// Packed dual-FMA (sm_100+ only; 2x fp32 FMA throughput vs FFMA-3reg)
__device__ __forceinline__ ull fma2(ull a, ull b, ull c) {
    ull d; asm("fma.rn.f32x2 %0, %1, %2, %3;" : "=l"(d) : "l"(a), "l"(b), "l"(c)); return d;
}

// ---------------------------------------------------------------------------
// Kernel 1: per-token quantum circuit -> g_P (duplicated layout)
// One thread per (b,s) row. Gates (depth*16*16 floats) live in smem; every
// thread in a warp reads the same gate element -> conflict-free broadcast LDS.
// ---------------------------------------------------------------------------
__global__ void prep_kernel(const int* __restrict__ ids,
                            const int* __restrict__ mask,
                            const float* __restrict__ We,
                            const float* __restrict__ gates,
                            int BS, int depth, int S, int B) {
    __shared__ float sg[2 * 256];
    for (int i = threadIdx.x; i < depth * 256; i += blockDim.x) sg[i] = gates[i];
    __syncthreads();

    int m = blockIdx.x * blockDim.x + threadIdx.x;
    if (m >= BS) return;

    int tok = ids[m];
    float e[16], st[16];
    const float4* wr = (const float4*)(We + (size_t)tok * 16);
#pragma unroll
    for (int q = 0; q < 4; q++) {
        float4 v = wr[q];
        e[4*q+0] = v.x; e[4*q+1] = v.y; e[4*q+2] = v.z; e[4*q+3] = v.w;
    }
    // normalize: x / (||x|| + 1e-12)
    float nrm = 0.f;
#pragma unroll
    for (int k = 0; k < 16; k++) nrm += e[k] * e[k];
    float inv = 1.f / (sqrtf(nrm) + 1e-12f);
#pragma unroll
    for (int k = 0; k < 16; k++) { e[k] *= inv; st[k] = e[k]; }

    // noisy circuit: per layer: gate matmul, decoherence*depol fused, normalize
    for (int l = 0; l < depth; l++) {
        float tmp[16];
#pragma unroll
        for (int o = 0; o < 16; o++) {
            float acc = 0.f;
#pragma unroll
            for (int d = 0; d < 16; d++) acc += st[d] * sg[l*256 + o*16 + d];
            tmp[o] = acc;
        }
        float s2 = 0.f;
#pragma unroll
        for (int o = 0; o < 16; o++) {
            // (1-DECOHERENCE) then (1-DEPOL)*x + DEPOL/dim  ==  x*0.9801 + 0.000625
            float x = tmp[o] * (0.99f * 0.99f) + (0.01f / 16.f);
            st[o] = x; s2 += x * x;
        }
        inv = 1.f / (sqrtf(s2) + 1e-12f);
#pragma unroll
        for (int o = 0; o < 16; o++) st[o] *= inv;
    }
    // measurement error mix
#pragma unroll
    for (int k = 0; k < 16; k++) st[k] = st[k] * 0.99f + (0.01f / 16.f);

    // per-position gate: circuit applied only if mask[:, s] all nonzero
    int s = m % S;
    bool ap = true;
    for (int b = 0; b < B; b++) ap = ap && (mask[b * S + s] != 0);

    // write duplicated: g_P[m][2k] = g_P[m][2k+1] = processed[k]
    float4* dst = (float4*)(g_P + (size_t)m * 32);
#pragma unroll
    for (int q = 0; q < 8; q++) {
        float a  = ap ? st[2*q]   : e[2*q];
        float b2 = ap ? st[2*q+1] : e[2*q+1];
        dst[q] = make_float4(a, a, b2, b2);
    }
}

// ---------------------------------------------------------------------------
// Kernel 2: out[M=4096, V=32000] = P @ W_out^T + b_out
// CTA = 256 threads, each thread owns 4 consecutive vocab columns.
// Column pairs packed into f32x2 W registers (hoisted); P multiplicand pairs
// come straight from the duplicated smem tile via broadcast LDS.
// Per row per thread: 32x fma.rn.f32x2 + 1x STG.128 (coalesced across warp).
// ---------------------------------------------------------------------------
#define MTILE 256

__global__ __launch_bounds__(256, 2)
void out_gemm_kernel(const float* __restrict__ Wout,
                     const float* __restrict__ bout,
                     float* __restrict__ out, int V) {
    __shared__ float sP[MTILE * 32];   // 32 KB duplicated-P tile

    int row0 = blockIdx.y * MTILE;
    // cooperative tile load: MTILE*32 floats = 2048 float4, 8 per thread
    {
        const float4* src = (const float4*)(g_P + (size_t)row0 * 32);
        float4* dst = (float4*)sP;
#pragma unroll
        for (int i = threadIdx.x; i < MTILE * 8; i += 256) dst[i] = src[i];
    }
    __syncthreads();

    int v0 = blockIdx.x * 1024 + threadIdx.x * 4;
    if (v0 >= V) return;   // V % 4 == 0, so no partial groups

    // Load + pack W columns: w2[c][k] = {Wout[v0+2c][k], Wout[v0+2c+1][k]}
    ull w2[2][16];
#pragma unroll
    for (int c = 0; c < 2; c++) {
        const float4* wa = (const float4*)(Wout + (size_t)(v0 + 2*c)     * 16);
        const float4* wb = (const float4*)(Wout + (size_t)(v0 + 2*c + 1) * 16);
#pragma unroll
        for (int q = 0; q < 4; q++) {
            float4 A = wa[q], Bv = wb[q];
            w2[c][4*q+0] = pack2(A.x, Bv.x);
            w2[c][4*q+1] = pack2(A.y, Bv.y);
            w2[c][4*q+2] = pack2(A.z, Bv.z);
            w2[c][4*q+3] = pack2(A.w, Bv.w);
        }
    }
    float4 bb = *(const float4*)(bout + v0);
    ull bias0 = pack2(bb.x, bb.y);
    ull bias1 = pack2(bb.z, bb.w);

    float* outp = out + (size_t)row0 * V + v0;
#pragma unroll 2
    for (int m = 0; m < MTILE; m++) {
        const ull* pp = (const ull*)(sP + m * 32);  // 16 packed {p,p} pairs
        ull a0 = bias0, a1 = bias1;
#pragma unroll
        for (int k = 0; k < 16; k++) {
            ull p2 = pp[k];                // broadcast LDS
            a0 = fma2(p2, w2[0][k], a0);   // columns v0, v0+1
            a1 = fma2(p2, w2[1][k], a1);   // columns v0+2, v0+3
        }
        float4 r;
        unpack2(a0, r.x, r.y);
        unpack2(a1, r.z, r.w);
        *(float4*)(outp + (size_t)m * V) = r;
    }
}

// ---------------------------------------------------------------------------
// Launch
// ---------------------------------------------------------------------------
extern "C" void kernel_launch(void* const* d_in, const int* in_sizes, int n_in,
                              void* d_out, int out_size) {
    const int*   ids   = (const int*)d_in[0];
    const int*   mask  = (const int*)d_in[1];
    const float* We    = (const float*)d_in[2];
    const float* gates = (const float*)d_in[3];
    const float* Wout  = (const float*)d_in[4];
    const float* bout  = (const float*)d_in[5];
    float* out = (float*)d_out;

    int BS    = in_sizes[0];          // B*S = 4096
    int V     = in_sizes[5];          // 32000
    int depth = in_sizes[3] / 256;    // 2
    int S     = 2048;                 // problem shape (fixed)
    int B     = BS / S;               // 2

    prep_kernel<<<(BS + 255) / 256, 256>>>(ids, mask, We, gates, BS, depth, S, B);

    dim3 grid((V + 1023) / 1024, BS / MTILE);
    out_gemm_kernel<<<grid, 256>>>(Wout, bout, out, V);
}

// round 3
// speedup vs baseline: 1.0724x; 1.0724x over previous
#include <cuda_runtime.h>

typedef unsigned long long ull;

// Scratch: processed states, natural layout [4096 rows x 16 floats] = 256 KB.
__device__ __align__(16) float g_P[4096 * 16];

__device__ __forceinline__ ull pack2(float lo, float hi) {
    ull r; asm("mov.b64 %0, {%1, %2};" : "=l"(r) : "f"(lo), "f"(hi)); return r;
}
__device__ __forceinline__ float hadd2(ull v) {
    float lo, hi; asm("mov.b64 {%0, %1}, %2;" : "=f"(lo), "=f"(hi) : "l"(v));
    return lo + hi;
}
// Packed dual-FMA (sm_100+ only; 2x fp32 FMA throughput vs FFMA-3reg)
__device__ __forceinline__ ull fma2(ull a, ull b, ull c) {
    ull d; asm("fma.rn.f32x2 %0, %1, %2, %3;" : "=l"(d) : "l"(a), "l"(b), "l"(c)); return d;
}

// ---------------------------------------------------------------------------
// Kernel 1: per-token quantum circuit -> g_P (natural layout)
// ---------------------------------------------------------------------------
__global__ void prep_kernel(const int* __restrict__ ids,
                            const int* __restrict__ mask,
                            const float* __restrict__ We,
                            const float* __restrict__ gates,
                            int BS, int depth, int S, int B) {
    __shared__ float sg[2 * 256];
    for (int i = threadIdx.x; i < depth * 256; i += blockDim.x) sg[i] = gates[i];
    __syncthreads();

    int m = blockIdx.x * blockDim.x + threadIdx.x;
    if (m >= BS) return;

    int tok = ids[m];
    float e[16], st[16];
    const float4* wr = (const float4*)(We + (size_t)tok * 16);
#pragma unroll
    for (int q = 0; q < 4; q++) {
        float4 v = wr[q];
        e[4*q+0] = v.x; e[4*q+1] = v.y; e[4*q+2] = v.z; e[4*q+3] = v.w;
    }
    float nrm = 0.f;
#pragma unroll
    for (int k = 0; k < 16; k++) nrm += e[k] * e[k];
    float inv = 1.f / (sqrtf(nrm) + 1e-12f);
#pragma unroll
    for (int k = 0; k < 16; k++) { e[k] *= inv; st[k] = e[k]; }

    for (int l = 0; l < depth; l++) {
        float tmp[16];
#pragma unroll
        for (int o = 0; o < 16; o++) {
            float acc = 0.f;
#pragma unroll
            for (int d = 0; d < 16; d++) acc += st[d] * sg[l*256 + o*16 + d];
            tmp[o] = acc;
        }
        float s2 = 0.f;
#pragma unroll
        for (int o = 0; o < 16; o++) {
            // (1-DECOHERENCE)*(1-DEPOL)*x + DEPOL/dim
            float x = tmp[o] * (0.99f * 0.99f) + (0.01f / 16.f);
            st[o] = x; s2 += x * x;
        }
        inv = 1.f / (sqrtf(s2) + 1e-12f);
#pragma unroll
        for (int o = 0; o < 16; o++) st[o] *= inv;
    }
#pragma unroll
    for (int k = 0; k < 16; k++) st[k] = st[k] * 0.99f + (0.01f / 16.f);

    int s = m % S;
    bool ap = true;
    for (int b = 0; b < B; b++) ap = ap && (mask[b * S + s] != 0);

    float4* dst = (float4*)(g_P + (size_t)m * 16);
#pragma unroll
    for (int q = 0; q < 4; q++) {
        dst[q] = make_float4(ap ? st[4*q]   : e[4*q],
                             ap ? st[4*q+1] : e[4*q+1],
                             ap ? st[4*q+2] : e[4*q+2],
                             ap ? st[4*q+3] : e[4*q+3]);
    }
}

// ---------------------------------------------------------------------------
// Kernel 2: out[4096, 32000] = P @ W_out^T + b_out
// MTILE=64 rows/CTA (2048 CTAs -> ~99% wave utilization), 256 threads,
// 4 vocab columns per thread. Accumulators are paired over K:
//   acc_c = { sum_k even p*w , sum_k odd p*w }  -> one horizontal add per col.
// P comes as natural {p_2k,p_2k+1} pairs via 4x LDS.128 per row (4x less
// crossbar pressure than the duplicated layout), double-buffered across rows.
// ---------------------------------------------------------------------------
#define MTILE 64

__global__ __launch_bounds__(256, 2)
void out_gemm_kernel(const float* __restrict__ Wout,
                     const float* __restrict__ bout,
                     float* __restrict__ out, int V) {
    __shared__ __align__(16) ull sP[MTILE * 8];   // 4 KB natural-pair tile

    int row0 = blockIdx.y * MTILE;
    // cooperative tile load: MTILE*16 floats = 256 float4 -> 1 per thread
    ((float4*)sP)[threadIdx.x] =
        ((const float4*)(g_P + (size_t)row0 * 16))[threadIdx.x];
    __syncthreads();

    int v0 = blockIdx.x * 1024 + threadIdx.x * 4;
    if (v0 >= V) return;

    // W pairs are natural-adjacent: w2[c][k] = {W[v0+c][2k], W[v0+c][2k+1]}
    ull w2[4][8];
#pragma unroll
    for (int c = 0; c < 4; c++) {
        const float4* wc = (const float4*)(Wout + (size_t)(v0 + c) * 16);
#pragma unroll
        for (int q = 0; q < 4; q++) {
            float4 t = wc[q];
            w2[c][2*q+0] = pack2(t.x, t.y);
            w2[c][2*q+1] = pack2(t.z, t.w);
        }
    }
    float4 bb = *(const float4*)(bout + v0);
    // bias folded into acc init: hadd({b,0} + sums) = sum + b
    ull binit[4] = { pack2(bb.x, 0.f), pack2(bb.y, 0.f),
                     pack2(bb.z, 0.f), pack2(bb.w, 0.f) };

    float* outp = out + (size_t)row0 * V + v0;

    ull pA[8], pB[8];
    // preload row 0 into A (4x LDS.128)
    {
        const ulonglong2* r = (const ulonglong2*)(sP);
#pragma unroll
        for (int q = 0; q < 4; q++) { ulonglong2 t = r[q]; pA[2*q] = t.x; pA[2*q+1] = t.y; }
    }

#pragma unroll 1
    for (int m = 0; m < MTILE; m += 2) {
        // prefetch row m+1 into B
        {
            const ulonglong2* r = (const ulonglong2*)(sP + (m + 1) * 8);
#pragma unroll
            for (int q = 0; q < 4; q++) { ulonglong2 t = r[q]; pB[2*q] = t.x; pB[2*q+1] = t.y; }
        }
        // compute row m from A
        {
            ull a0 = binit[0], a1 = binit[1], a2 = binit[2], a3 = binit[3];
#pragma unroll
            for (int k = 0; k < 8; k++) {
                ull p = pA[k];
                a0 = fma2(p, w2[0][k], a0);
                a1 = fma2(p, w2[1][k], a1);
                a2 = fma2(p, w2[2][k], a2);
                a3 = fma2(p, w2[3][k], a3);
            }
            float4 r = make_float4(hadd2(a0), hadd2(a1), hadd2(a2), hadd2(a3));
            *(float4*)outp = r;
            outp += V;
        }
        // prefetch row m+2 into A
        if (m + 2 < MTILE) {
            const ulonglong2* r = (const ulonglong2*)(sP + (m + 2) * 8);
#pragma unroll
            for (int q = 0; q < 4; q++) { ulonglong2 t = r[q]; pA[2*q] = t.x; pA[2*q+1] = t.y; }
        }
        // compute row m+1 from B
        {
            ull a0 = binit[0], a1 = binit[1], a2 = binit[2], a3 = binit[3];
#pragma unroll
            for (int k = 0; k < 8; k++) {
                ull p = pB[k];
                a0 = fma2(p, w2[0][k], a0);
                a1 = fma2(p, w2[1][k], a1);
                a2 = fma2(p, w2[2][k], a2);
                a3 = fma2(p, w2[3][k], a3);
            }
            float4 r = make_float4(hadd2(a0), hadd2(a1), hadd2(a2), hadd2(a3));
            *(float4*)outp = r;
            outp += V;
        }
    }
}

// ---------------------------------------------------------------------------
// Launch
// ---------------------------------------------------------------------------
extern "C" void kernel_launch(void* const* d_in, const int* in_sizes, int n_in,
                              void* d_out, int out_size) {
    const int*   ids   = (const int*)d_in[0];
    const int*   mask  = (const int*)d_in[1];
    const float* We    = (const float*)d_in[2];
    const float* gates = (const float*)d_in[3];
    const float* Wout  = (const float*)d_in[4];
    const float* bout  = (const float*)d_in[5];
    float* out = (float*)d_out;

    int BS    = in_sizes[0];          // B*S = 4096
    int V     = in_sizes[5];          // 32000
    int depth = in_sizes[3] / 256;    // 2
    int S     = 2048;                 // problem shape (fixed)
    int B     = BS / S;               // 2

    prep_kernel<<<(BS + 127) / 128, 128>>>(ids, mask, We, gates, BS, depth, S, B);

    dim3 grid((V + 1023) / 1024, BS / MTILE);
    out_gemm_kernel<<<grid, 256>>>(Wout, bout, out, V);
}